// round 1
// baseline (speedup 1.0000x reference)
#include <cuda_runtime.h>
#include <math.h>

#define TT 4096   // tokens (B*S)
#define HH 1024   // hidden
#define II 2048   // intermediate
#define EE 8      // experts
// TOP_K = 2

// -------- scratch (static device arrays: no allocs allowed) --------
__device__ int   g_cnt[EE];
__device__ float g_psum[EE];
__device__ float g_zsum;
__device__ int   g_tok[EE * TT];
__device__ float g_wt[EE * TT];
__device__ float g_act_sh[(size_t)TT * II];           // shared-expert activations
__device__ float g_act_rt[(size_t)EE * TT * II];      // routed activations (per-expert capacity T)

// -------------------- init --------------------
__global__ void k_init() {
    int i = threadIdx.x;
    if (i < EE) { g_cnt[i] = 0; g_psum[i] = 0.f; }
    if (i == 0) g_zsum = 0.f;
}

// -------------------- router --------------------
// 1 warp per token. 128 threads/block -> 4 tokens/block. Grid = TT/4.
__global__ void k_router(const float* __restrict__ x, const float* __restrict__ rw,
                         float* __restrict__ out) {
    __shared__ float s_p[EE];
    __shared__ float s_z;
    if (threadIdx.x < EE) s_p[threadIdx.x] = 0.f;
    if (threadIdx.x == 0) s_z = 0.f;
    __syncthreads();

    const int warp = threadIdx.x >> 5;
    const int lane = threadIdx.x & 31;
    const int t = blockIdx.x * 4 + warp;   // exact: grid*warps == TT

    float acc[EE];
#pragma unroll
    for (int e = 0; e < EE; e++) acc[e] = 0.f;
    const float* xr = x + (size_t)t * HH;
    for (int jj = 0; jj < HH / 32; jj++) {
        int j = jj * 32 + lane;
        float xv = xr[j];
        const float* r = rw + j * EE;
#pragma unroll
        for (int e = 0; e < EE; e++) acc[e] = fmaf(xv, r[e], acc[e]);
    }
#pragma unroll
    for (int e = 0; e < EE; e++) {
#pragma unroll
        for (int o = 16; o > 0; o >>= 1) acc[e] += __shfl_xor_sync(0xffffffffu, acc[e], o);
    }

    if (lane == 0) {
        // logits out
        float* lo = out + (size_t)TT * HH + 2 + (size_t)t * EE;
        float mx = acc[0];
#pragma unroll
        for (int e = 1; e < EE; e++) mx = fmaxf(mx, acc[e]);
        float p[EE];
        float se = 0.f;
#pragma unroll
        for (int e = 0; e < EE; e++) { p[e] = expf(acc[e] - mx); se += p[e]; }
        float lse = logf(se) + mx;
        atomicAdd(&s_z, lse * lse);
        float inv = 1.f / se;
#pragma unroll
        for (int e = 0; e < EE; e++) {
            p[e] *= inv;
            lo[e] = acc[e];
            atomicAdd(&s_p[e], p[e]);
        }
        // top-2 (strict > keeps lowest index on ties, matching lax.top_k)
        int i0 = 0;
#pragma unroll
        for (int e = 1; e < EE; e++) if (p[e] > p[i0]) i0 = e;
        int i1 = -1;
#pragma unroll
        for (int e = 0; e < EE; e++) {
            if (e == i0) continue;
            if (i1 < 0 || p[e] > p[i1]) i1 = e;
        }
        float ws = p[i0] + p[i1];
        float w0 = p[i0] / ws, w1 = p[i1] / ws;
        int pos0 = atomicAdd(&g_cnt[i0], 1);
        g_tok[i0 * TT + pos0] = t; g_wt[i0 * TT + pos0] = w0;
        int pos1 = atomicAdd(&g_cnt[i1], 1);
        g_tok[i1 * TT + pos1] = t; g_wt[i1 * TT + pos1] = w1;
    }
    __syncthreads();
    if (threadIdx.x < EE) atomicAdd(&g_psum[threadIdx.x], s_p[threadIdx.x]);
    if (threadIdx.x == 0) atomicAdd(&g_zsum, s_z);
}

// -------------------- GEMM1: act = silu(X@Wg) * (X@Wu) --------------------
// Tiles: BM=128, BN=64, BK=16. 256 threads, each computes 8x4 for gate AND up.
// blockIdx.z: 0..7 routed experts (gathered rows), 8 = shared expert (all rows).
__global__ __launch_bounds__(256) void k_gemm1(
    const float* __restrict__ x,
    const float* __restrict__ gate_w, const float* __restrict__ up_w,
    const float* __restrict__ sgw, const float* __restrict__ suw)
{
    const int e = blockIdx.z;
    const bool se_pass = (e == EE);
    const int nrows = se_pass ? TT : g_cnt[e];
    const int m0 = blockIdx.y * 128;
    if (m0 >= nrows) return;
    const int n0 = blockIdx.x * 64;

    const float* __restrict__ Bg = se_pass ? sgw : gate_w + (size_t)e * HH * II;
    const float* __restrict__ Bu = se_pass ? suw : up_w + (size_t)e * HH * II;
    const int*   __restrict__ toks = se_pass ? nullptr : (g_tok + e * TT);
    float*       __restrict__ Out = se_pass ? g_act_sh : (g_act_rt + (size_t)e * TT * II);

    __shared__ __align__(16) float As[16][132];
    __shared__ __align__(16) float Bgs[16][64];
    __shared__ __align__(16) float Bus[16][64];

    const int tid = threadIdx.x;
    const int tx = tid & 15;        // n sub-tile
    const int ty = tid >> 4;        // m sub-tile

    // precompute gathered source rows for this thread's two A float4 loads
    int src[2], kcol[2], arow[2];
#pragma unroll
    for (int l = 0; l < 2; l++) {
        int idx = tid + l * 256;
        arow[l] = idx >> 2;                 // 0..127
        kcol[l] = (idx & 3) * 4;            // 0,4,8,12
        int row = m0 + arow[l];
        int rr = (row < nrows) ? row : (nrows - 1);
        src[l] = toks ? toks[rr] : rr;
    }
    const int brow = tid >> 4;
    const int bcol = (tid & 15) * 4;

    float accg[8][4], accu[8][4];
#pragma unroll
    for (int i = 0; i < 8; i++)
#pragma unroll
        for (int j = 0; j < 4; j++) { accg[i][j] = 0.f; accu[i][j] = 0.f; }

    for (int k0 = 0; k0 < HH; k0 += 16) {
#pragma unroll
        for (int l = 0; l < 2; l++) {
            float4 v = *reinterpret_cast<const float4*>(x + (size_t)src[l] * HH + k0 + kcol[l]);
            As[kcol[l] + 0][arow[l]] = v.x;
            As[kcol[l] + 1][arow[l]] = v.y;
            As[kcol[l] + 2][arow[l]] = v.z;
            As[kcol[l] + 3][arow[l]] = v.w;
        }
        {
            *reinterpret_cast<float4*>(&Bgs[brow][bcol]) =
                *reinterpret_cast<const float4*>(Bg + (size_t)(k0 + brow) * II + n0 + bcol);
            *reinterpret_cast<float4*>(&Bus[brow][bcol]) =
                *reinterpret_cast<const float4*>(Bu + (size_t)(k0 + brow) * II + n0 + bcol);
        }
        __syncthreads();
#pragma unroll
        for (int k = 0; k < 16; k++) {
            float4 a0 = *reinterpret_cast<const float4*>(&As[k][ty * 8]);
            float4 a1 = *reinterpret_cast<const float4*>(&As[k][ty * 8 + 4]);
            float4 bg = *reinterpret_cast<const float4*>(&Bgs[k][tx * 4]);
            float4 bu = *reinterpret_cast<const float4*>(&Bus[k][tx * 4]);
            float a[8] = {a0.x, a0.y, a0.z, a0.w, a1.x, a1.y, a1.z, a1.w};
            float bgv[4] = {bg.x, bg.y, bg.z, bg.w};
            float buv[4] = {bu.x, bu.y, bu.z, bu.w};
#pragma unroll
            for (int i = 0; i < 8; i++)
#pragma unroll
                for (int j = 0; j < 4; j++) {
                    accg[i][j] = fmaf(a[i], bgv[j], accg[i][j]);
                    accu[i][j] = fmaf(a[i], buv[j], accu[i][j]);
                }
        }
        __syncthreads();
    }

#pragma unroll
    for (int i = 0; i < 8; i++) {
        int row = m0 + ty * 8 + i;
        if (row >= nrows) continue;
        float4 v;
        float g;
        g = accg[i][0]; v.x = accu[i][0] * (g / (1.f + expf(-g)));
        g = accg[i][1]; v.y = accu[i][1] * (g / (1.f + expf(-g)));
        g = accg[i][2]; v.z = accu[i][2] * (g / (1.f + expf(-g)));
        g = accg[i][3]; v.w = accu[i][3] * (g / (1.f + expf(-g)));
        *reinterpret_cast<float4*>(Out + (size_t)row * II + n0 + tx * 4) = v;
    }
}

// -------------------- GEMM2: out += w * (act @ Wd) --------------------
// shared_pass=1: writes out directly (initializes routed region).
// shared_pass=0: per-expert gathered rows, weighted atomicAdd scatter.
__global__ __launch_bounds__(256) void k_gemm2(
    const float* __restrict__ down_w, const float* __restrict__ sdw,
    float* __restrict__ out, int shared_pass)
{
    const int e = shared_pass ? EE : blockIdx.z;
    const int nrows = shared_pass ? TT : g_cnt[e];
    const int m0 = blockIdx.y * 128;
    if (m0 >= nrows) return;
    const int n0 = blockIdx.x * 64;

    const float* __restrict__ B = shared_pass ? sdw : down_w + (size_t)e * II * HH;
    const float* __restrict__ A = shared_pass ? g_act_sh : (g_act_rt + (size_t)e * TT * II);

    __shared__ __align__(16) float As[16][132];
    __shared__ __align__(16) float Bs[16][64];

    const int tid = threadIdx.x;
    const int tx = tid & 15;
    const int ty = tid >> 4;

    int srow[2], kcol[2], arow[2];
#pragma unroll
    for (int l = 0; l < 2; l++) {
        int idx = tid + l * 256;
        arow[l] = idx >> 2;
        kcol[l] = (idx & 3) * 4;
        int row = m0 + arow[l];
        srow[l] = (row < nrows) ? row : (nrows - 1);
    }
    const int brow = tid >> 4;
    const int bcol = (tid & 15) * 4;

    float acc[8][4];
#pragma unroll
    for (int i = 0; i < 8; i++)
#pragma unroll
        for (int j = 0; j < 4; j++) acc[i][j] = 0.f;

    for (int k0 = 0; k0 < II; k0 += 16) {
#pragma unroll
        for (int l = 0; l < 2; l++) {
            float4 v = *reinterpret_cast<const float4*>(A + (size_t)srow[l] * II + k0 + kcol[l]);
            As[kcol[l] + 0][arow[l]] = v.x;
            As[kcol[l] + 1][arow[l]] = v.y;
            As[kcol[l] + 2][arow[l]] = v.z;
            As[kcol[l] + 3][arow[l]] = v.w;
        }
        *reinterpret_cast<float4*>(&Bs[brow][bcol]) =
            *reinterpret_cast<const float4*>(B + (size_t)(k0 + brow) * HH + n0 + bcol);
        __syncthreads();
#pragma unroll
        for (int k = 0; k < 16; k++) {
            float4 a0 = *reinterpret_cast<const float4*>(&As[k][ty * 8]);
            float4 a1 = *reinterpret_cast<const float4*>(&As[k][ty * 8 + 4]);
            float4 b  = *reinterpret_cast<const float4*>(&Bs[k][tx * 4]);
            float a[8] = {a0.x, a0.y, a0.z, a0.w, a1.x, a1.y, a1.z, a1.w};
            float bv[4] = {b.x, b.y, b.z, b.w};
#pragma unroll
            for (int i = 0; i < 8; i++)
#pragma unroll
                for (int j = 0; j < 4; j++)
                    acc[i][j] = fmaf(a[i], bv[j], acc[i][j]);
        }
        __syncthreads();
    }

    if (shared_pass) {
#pragma unroll
        for (int i = 0; i < 8; i++) {
            int row = m0 + ty * 8 + i;
            if (row >= nrows) continue;
            float4 v = make_float4(acc[i][0], acc[i][1], acc[i][2], acc[i][3]);
            *reinterpret_cast<float4*>(out + (size_t)row * HH + n0 + tx * 4) = v;
        }
    } else {
        const int*   toks = g_tok + e * TT;
        const float* wts  = g_wt + e * TT;
#pragma unroll
        for (int i = 0; i < 8; i++) {
            int row = m0 + ty * 8 + i;
            if (row >= nrows) continue;
            int t = toks[row];
            float w = wts[row];
            float* dst = out + (size_t)t * HH + n0 + tx * 4;
            atomicAdd(dst + 0, w * acc[i][0]);
            atomicAdd(dst + 1, w * acc[i][1]);
            atomicAdd(dst + 2, w * acc[i][2]);
            atomicAdd(dst + 3, w * acc[i][3]);
        }
    }
}

// -------------------- finalize losses --------------------
__global__ void k_final(float* __restrict__ out) {
    if (threadIdx.x == 0) {
        float aux = 0.f;
        for (int e = 0; e < EE; e++) aux += (float)g_cnt[e] * g_psum[e];
        // E * sum(cnt/(K*T) * psum/T)
        aux = aux * (float)EE / ((float)(2) * (float)TT * (float)TT);
        out[(size_t)TT * HH + 0] = aux;
        out[(size_t)TT * HH + 1] = g_zsum / (float)TT;
    }
}

// -------------------- launch --------------------
extern "C" void kernel_launch(void* const* d_in, const int* in_sizes, int n_in,
                              void* d_out, int out_size) {
    const float* x   = (const float*)d_in[0];
    const float* rw  = (const float*)d_in[1];
    const float* gw  = (const float*)d_in[2];
    const float* uw  = (const float*)d_in[3];
    const float* dw  = (const float*)d_in[4];
    const float* sgw = (const float*)d_in[5];
    const float* suw = (const float*)d_in[6];
    const float* sdw = (const float*)d_in[7];
    float* out = (float*)d_out;

    k_init<<<1, 32>>>();
    k_router<<<TT / 4, 128>>>(x, rw, out);
    // GEMM1: z in [0,8): routed experts; z==8: shared expert
    k_gemm1<<<dim3(II / 64, TT / 128, EE + 1), 256>>>(x, gw, uw, sgw, suw);
    // shared down-proj writes out (initializes routed region)...
    k_gemm2<<<dim3(HH / 64, TT / 128, 1), 256>>>(dw, sdw, out, 1);
    // ...then routed experts atomically accumulate on top
    k_gemm2<<<dim3(HH / 64, TT / 128, EE), 256>>>(dw, sdw, out, 0);
    k_final<<<1, 32>>>(out);
}

// round 2
// speedup vs baseline: 2.4274x; 2.4274x over previous
#include <cuda_runtime.h>
#include <math.h>
#include <stdint.h>

#define TT 4096   // tokens (B*S)
#define HH 1024   // hidden
#define II 2048   // intermediate
#define EE 8      // experts
// TOP_K = 2

// -------- scratch (static device arrays: no allocs allowed) --------
__device__ int   g_cnt[EE];
__device__ float g_psum[EE];
__device__ float g_zsum;
__device__ int   g_tok[EE * TT];
__device__ float g_wt[EE * TT];
__device__ float g_act_sh[(size_t)TT * II];           // shared-expert activations
__device__ float g_act_rt[(size_t)EE * TT * II];      // routed activations (per-expert capacity T)

// -------------------- helpers --------------------
__device__ __forceinline__ uint32_t f2tf(float f) {
    uint32_t o; asm("cvt.rna.tf32.f32 %0, %1;" : "=r"(o) : "f"(f)); return o;
}
__device__ __forceinline__ void ldsm4(uint32_t& r0, uint32_t& r1, uint32_t& r2, uint32_t& r3,
                                      uint32_t addr) {
    asm volatile("ldmatrix.sync.aligned.m8n8.x4.shared.b16 {%0,%1,%2,%3}, [%4];"
                 : "=r"(r0), "=r"(r1), "=r"(r2), "=r"(r3) : "r"(addr));
}
__device__ __forceinline__ void mma_tf32(float* c, const uint32_t* a, uint32_t b0, uint32_t b1) {
    asm volatile("mma.sync.aligned.m16n8k8.row.col.f32.tf32.tf32.f32 "
                 "{%0,%1,%2,%3}, {%4,%5,%6,%7}, {%8,%9}, {%0,%1,%2,%3};"
                 : "+f"(c[0]), "+f"(c[1]), "+f"(c[2]), "+f"(c[3])
                 : "r"(a[0]), "r"(a[1]), "r"(a[2]), "r"(a[3]), "r"(b0), "r"(b1));
}

// -------------------- init --------------------
__global__ void k_init() {
    int i = threadIdx.x;
    if (i < EE) { g_cnt[i] = 0; g_psum[i] = 0.f; }
    if (i == 0) g_zsum = 0.f;
}

// -------------------- router (unchanged from R1 — known good) --------------------
__global__ void k_router(const float* __restrict__ x, const float* __restrict__ rw,
                         float* __restrict__ out) {
    __shared__ float s_p[EE];
    __shared__ float s_z;
    if (threadIdx.x < EE) s_p[threadIdx.x] = 0.f;
    if (threadIdx.x == 0) s_z = 0.f;
    __syncthreads();

    const int warp = threadIdx.x >> 5;
    const int lane = threadIdx.x & 31;
    const int t = blockIdx.x * 4 + warp;

    float acc[EE];
#pragma unroll
    for (int e = 0; e < EE; e++) acc[e] = 0.f;
    const float* xr = x + (size_t)t * HH;
    for (int jj = 0; jj < HH / 32; jj++) {
        int j = jj * 32 + lane;
        float xv = xr[j];
        const float* r = rw + j * EE;
#pragma unroll
        for (int e = 0; e < EE; e++) acc[e] = fmaf(xv, r[e], acc[e]);
    }
#pragma unroll
    for (int e = 0; e < EE; e++) {
#pragma unroll
        for (int o = 16; o > 0; o >>= 1) acc[e] += __shfl_xor_sync(0xffffffffu, acc[e], o);
    }

    if (lane == 0) {
        float* lo = out + (size_t)TT * HH + 2 + (size_t)t * EE;
        float mx = acc[0];
#pragma unroll
        for (int e = 1; e < EE; e++) mx = fmaxf(mx, acc[e]);
        float p[EE];
        float se = 0.f;
#pragma unroll
        for (int e = 0; e < EE; e++) { p[e] = expf(acc[e] - mx); se += p[e]; }
        float lse = logf(se) + mx;
        atomicAdd(&s_z, lse * lse);
        float inv = 1.f / se;
#pragma unroll
        for (int e = 0; e < EE; e++) {
            p[e] *= inv;
            lo[e] = acc[e];
            atomicAdd(&s_p[e], p[e]);
        }
        int i0 = 0;
#pragma unroll
        for (int e = 1; e < EE; e++) if (p[e] > p[i0]) i0 = e;
        int i1 = -1;
#pragma unroll
        for (int e = 0; e < EE; e++) {
            if (e == i0) continue;
            if (i1 < 0 || p[e] > p[i1]) i1 = e;
        }
        float ws = p[i0] + p[i1];
        float w0 = p[i0] / ws, w1 = p[i1] / ws;
        int pos0 = atomicAdd(&g_cnt[i0], 1);
        g_tok[i0 * TT + pos0] = t; g_wt[i0 * TT + pos0] = w0;
        int pos1 = atomicAdd(&g_cnt[i1], 1);
        g_tok[i1 * TT + pos1] = t; g_wt[i1 * TT + pos1] = w1;
    }
    __syncthreads();
    if (threadIdx.x < EE) atomicAdd(&g_psum[threadIdx.x], s_p[threadIdx.x]);
    if (threadIdx.x == 0) atomicAdd(&g_zsum, s_z);
}

// ==================== GEMM1 (tensor-core tf32, dual gate+up) ====================
// BM=128, BN=64, BK=32. 256 threads = 8 warps (4 m x 2 n), warp tile 32x32.
// z: 0..7 routed experts (gathered rows), 8 = shared expert.
// Epilogue: silu(gate)*up -> g_act_*.
__global__ __launch_bounds__(256) void k_gemm1_tc(
    const float* __restrict__ x,
    const float* __restrict__ gw, const float* __restrict__ uw,
    const float* __restrict__ sgw, const float* __restrict__ suw)
{
    const int e = blockIdx.z;
    const bool sp = (e == EE);
    const int nrows = sp ? TT : g_cnt[e];
    const int m0 = blockIdx.y * 128;
    if (m0 >= nrows) return;
    const int n0 = blockIdx.x * 64;

    const float* __restrict__ Bg = sp ? sgw : gw + (size_t)e * HH * II;
    const float* __restrict__ Bu = sp ? suw : uw + (size_t)e * HH * II;
    const int*   __restrict__ toks = sp ? nullptr : (g_tok + e * TT);
    float*       __restrict__ Out = sp ? g_act_sh : (g_act_rt + (size_t)e * TT * II);

    __shared__ uint32_t As[128 * 36];   // [m][kpad=36]
    __shared__ uint32_t Bgs[32 * 72];   // [k][npad=72]
    __shared__ uint32_t Bus[32 * 72];

    const int tid = threadIdx.x;
    const int lane = tid & 31;
    const int warp = tid >> 5;
    const int wm = warp & 3;
    const int wn = warp >> 2;
    const int gid = lane >> 2;
    const int tig = lane & 3;

    // A staging: 4 float4/thread
    int arow[4], acol[4];
    const float* aptr[4];
#pragma unroll
    for (int l = 0; l < 4; l++) {
        int gi = l * 256 + tid;
        arow[l] = gi >> 3;
        acol[l] = (gi & 7) * 4;
        int r = m0 + arow[l];
        if (r >= nrows) r = nrows - 1;
        int src = toks ? toks[r] : r;
        aptr[l] = x + (size_t)src * HH + acol[l];
    }
    // B staging: 2 float4/thread per matrix
    int bk[2], bn[2];
#pragma unroll
    for (int l = 0; l < 2; l++) { int gi = l * 256 + tid; bk[l] = gi >> 4; bn[l] = (gi & 15) * 4; }

    // ldmatrix A addresses (per m-tile)
    uint32_t a_addr[2];
#pragma unroll
    for (int mt = 0; mt < 2; mt++) {
        int r = wm * 32 + mt * 16 + (lane & 15);
        int c = (lane >> 4) * 4;
        a_addr[mt] = (uint32_t)__cvta_generic_to_shared(&As[r * 36 + c]);
    }

    float accg[2][4][4], accu[2][4][4];
#pragma unroll
    for (int mt = 0; mt < 2; mt++)
#pragma unroll
        for (int nt = 0; nt < 4; nt++)
#pragma unroll
            for (int j = 0; j < 4; j++) { accg[mt][nt][j] = 0.f; accu[mt][nt][j] = 0.f; }

    float4 ar[4], bgr[2], bur[2];
    const int NK = HH / 32;

    // prologue: load tile 0
#pragma unroll
    for (int l = 0; l < 4; l++) ar[l] = *(const float4*)(aptr[l]);
#pragma unroll
    for (int l = 0; l < 2; l++) {
        bgr[l] = *(const float4*)(Bg + (size_t)bk[l] * II + n0 + bn[l]);
        bur[l] = *(const float4*)(Bu + (size_t)bk[l] * II + n0 + bn[l]);
    }

    for (int kt = 0; kt < NK; kt++) {
        // store staged regs -> smem
#pragma unroll
        for (int l = 0; l < 4; l++) {
            *(uint4*)&As[arow[l] * 36 + acol[l]] =
                make_uint4(f2tf(ar[l].x), f2tf(ar[l].y), f2tf(ar[l].z), f2tf(ar[l].w));
        }
#pragma unroll
        for (int l = 0; l < 2; l++) {
            *(uint4*)&Bgs[bk[l] * 72 + bn[l]] =
                make_uint4(f2tf(bgr[l].x), f2tf(bgr[l].y), f2tf(bgr[l].z), f2tf(bgr[l].w));
            *(uint4*)&Bus[bk[l] * 72 + bn[l]] =
                make_uint4(f2tf(bur[l].x), f2tf(bur[l].y), f2tf(bur[l].z), f2tf(bur[l].w));
        }
        __syncthreads();

        // prefetch next tile (LDG latency overlaps MMA below)
        if (kt + 1 < NK) {
            int k0 = (kt + 1) * 32;
#pragma unroll
            for (int l = 0; l < 4; l++) ar[l] = *(const float4*)(aptr[l] + k0);
#pragma unroll
            for (int l = 0; l < 2; l++) {
                bgr[l] = *(const float4*)(Bg + (size_t)(k0 + bk[l]) * II + n0 + bn[l]);
                bur[l] = *(const float4*)(Bu + (size_t)(k0 + bk[l]) * II + n0 + bn[l]);
            }
        }

        // compute 4 k-slices of 8
#pragma unroll
        for (int ks = 0; ks < 4; ks++) {
            uint32_t a[2][4];
            ldsm4(a[0][0], a[0][1], a[0][2], a[0][3], a_addr[0] + ks * 32);
            ldsm4(a[1][0], a[1][1], a[1][2], a[1][3], a_addr[1] + ks * 32);
            uint32_t bgf[4][2], buf_[4][2];
#pragma unroll
            for (int nt = 0; nt < 4; nt++) {
                int nn = wn * 32 + nt * 8 + gid;
                int kk = ks * 8 + tig;
                bgf[nt][0] = Bgs[kk * 72 + nn];
                bgf[nt][1] = Bgs[(kk + 4) * 72 + nn];
                buf_[nt][0] = Bus[kk * 72 + nn];
                buf_[nt][1] = Bus[(kk + 4) * 72 + nn];
            }
#pragma unroll
            for (int mt = 0; mt < 2; mt++)
#pragma unroll
                for (int nt = 0; nt < 4; nt++) {
                    mma_tf32(accg[mt][nt], a[mt], bgf[nt][0], bgf[nt][1]);
                    mma_tf32(accu[mt][nt], a[mt], buf_[nt][0], buf_[nt][1]);
                }
        }
        __syncthreads();
    }

    // epilogue: silu(gate)*up
#pragma unroll
    for (int mt = 0; mt < 2; mt++) {
#pragma unroll
        for (int i = 0; i < 2; i++) {
            int rl = m0 + wm * 32 + mt * 16 + i * 8 + gid;
            if (rl >= nrows) continue;
#pragma unroll
            for (int nt = 0; nt < 4; nt++) {
                int col = n0 + wn * 32 + nt * 8 + tig * 2;
                float g0 = accg[mt][nt][i * 2 + 0], g1 = accg[mt][nt][i * 2 + 1];
                float u0 = accu[mt][nt][i * 2 + 0], u1 = accu[mt][nt][i * 2 + 1];
                float2 v;
                v.x = u0 * (g0 / (1.f + expf(-g0)));
                v.y = u1 * (g1 / (1.f + expf(-g1)));
                *(float2*)(Out + (size_t)rl * II + col) = v;
            }
        }
    }
}

// ==================== GEMM2 (tensor-core tf32, down-proj) ====================
// BM=128, BN=128, BK=32. 8 warps (4 m x 2 n), warp tile 32x64.
// shared_pass=1: A=g_act_sh, plain stores (initializes out).
// shared_pass=0: per-expert gathered rows, weighted atomicAdd scatter.
__global__ __launch_bounds__(256) void k_gemm2_tc(
    const float* __restrict__ dw, const float* __restrict__ sdw,
    float* __restrict__ out, int shared_pass)
{
    const int e = shared_pass ? EE : blockIdx.z;
    const int nrows = shared_pass ? TT : g_cnt[e];
    const int m0 = blockIdx.y * 128;
    if (m0 >= nrows) return;
    const int n0 = blockIdx.x * 128;

    const float* __restrict__ B = shared_pass ? sdw : dw + (size_t)e * II * HH;
    const float* __restrict__ A = shared_pass ? g_act_sh : (g_act_rt + (size_t)e * TT * II);

    __shared__ uint32_t As[128 * 36];   // [m][kpad=36]
    __shared__ uint32_t Bs[32 * 136];   // [k][npad=136]

    const int tid = threadIdx.x;
    const int lane = tid & 31;
    const int warp = tid >> 5;
    const int wm = warp & 3;
    const int wn = warp >> 2;
    const int gid = lane >> 2;
    const int tig = lane & 3;

    // A staging: 4 float4/thread
    int arow[4], acol[4];
    const float* aptr[4];
#pragma unroll
    for (int l = 0; l < 4; l++) {
        int gi = l * 256 + tid;
        arow[l] = gi >> 3;
        acol[l] = (gi & 7) * 4;
        int r = m0 + arow[l];
        if (r >= nrows) r = nrows - 1;
        aptr[l] = A + (size_t)r * II + acol[l];
    }
    // B staging: 4 float4/thread (32 k-rows x 32 f4)
    int bk[4], bn[4];
#pragma unroll
    for (int l = 0; l < 4; l++) { int gi = l * 256 + tid; bk[l] = gi >> 5; bn[l] = (gi & 31) * 4; }

    uint32_t a_addr[2];
#pragma unroll
    for (int mt = 0; mt < 2; mt++) {
        int r = wm * 32 + mt * 16 + (lane & 15);
        int c = (lane >> 4) * 4;
        a_addr[mt] = (uint32_t)__cvta_generic_to_shared(&As[r * 36 + c]);
    }

    float acc[2][8][4];
#pragma unroll
    for (int mt = 0; mt < 2; mt++)
#pragma unroll
        for (int nt = 0; nt < 8; nt++)
#pragma unroll
            for (int j = 0; j < 4; j++) acc[mt][nt][j] = 0.f;

    float4 ar[4], br[4];
    const int NK = II / 32;

#pragma unroll
    for (int l = 0; l < 4; l++) ar[l] = *(const float4*)(aptr[l]);
#pragma unroll
    for (int l = 0; l < 4; l++)
        br[l] = *(const float4*)(B + (size_t)bk[l] * HH + n0 + bn[l]);

    for (int kt = 0; kt < NK; kt++) {
#pragma unroll
        for (int l = 0; l < 4; l++) {
            *(uint4*)&As[arow[l] * 36 + acol[l]] =
                make_uint4(f2tf(ar[l].x), f2tf(ar[l].y), f2tf(ar[l].z), f2tf(ar[l].w));
        }
#pragma unroll
        for (int l = 0; l < 4; l++) {
            *(uint4*)&Bs[bk[l] * 136 + bn[l]] =
                make_uint4(f2tf(br[l].x), f2tf(br[l].y), f2tf(br[l].z), f2tf(br[l].w));
        }
        __syncthreads();

        if (kt + 1 < NK) {
            int k0 = (kt + 1) * 32;
#pragma unroll
            for (int l = 0; l < 4; l++) ar[l] = *(const float4*)(aptr[l] + k0);
#pragma unroll
            for (int l = 0; l < 4; l++)
                br[l] = *(const float4*)(B + (size_t)(k0 + bk[l]) * HH + n0 + bn[l]);
        }

#pragma unroll
        for (int ks = 0; ks < 4; ks++) {
            uint32_t a[2][4];
            ldsm4(a[0][0], a[0][1], a[0][2], a[0][3], a_addr[0] + ks * 32);
            ldsm4(a[1][0], a[1][1], a[1][2], a[1][3], a_addr[1] + ks * 32);
            uint32_t bf[8][2];
#pragma unroll
            for (int nt = 0; nt < 8; nt++) {
                int nn = wn * 64 + nt * 8 + gid;
                int kk = ks * 8 + tig;
                bf[nt][0] = Bs[kk * 136 + nn];
                bf[nt][1] = Bs[(kk + 4) * 136 + nn];
            }
#pragma unroll
            for (int mt = 0; mt < 2; mt++)
#pragma unroll
                for (int nt = 0; nt < 8; nt++)
                    mma_tf32(acc[mt][nt], a[mt], bf[nt][0], bf[nt][1]);
        }
        __syncthreads();
    }

    // epilogue
#pragma unroll
    for (int mt = 0; mt < 2; mt++) {
#pragma unroll
        for (int i = 0; i < 2; i++) {
            int rl = m0 + wm * 32 + mt * 16 + i * 8 + gid;
            if (rl >= nrows) continue;
            if (shared_pass) {
#pragma unroll
                for (int nt = 0; nt < 8; nt++) {
                    int col = n0 + wn * 64 + nt * 8 + tig * 2;
                    float2 v = make_float2(acc[mt][nt][i * 2], acc[mt][nt][i * 2 + 1]);
                    *(float2*)(out + (size_t)rl * HH + col) = v;
                }
            } else {
                int t = g_tok[e * TT + rl];
                float w = g_wt[e * TT + rl];
                float* dst = out + (size_t)t * HH;
#pragma unroll
                for (int nt = 0; nt < 8; nt++) {
                    int col = n0 + wn * 64 + nt * 8 + tig * 2;
                    atomicAdd(dst + col, w * acc[mt][nt][i * 2]);
                    atomicAdd(dst + col + 1, w * acc[mt][nt][i * 2 + 1]);
                }
            }
        }
    }
}

// -------------------- finalize losses --------------------
__global__ void k_final(float* __restrict__ out) {
    if (threadIdx.x == 0) {
        float aux = 0.f;
        for (int e = 0; e < EE; e++) aux += (float)g_cnt[e] * g_psum[e];
        aux = aux * (float)EE / ((float)(2) * (float)TT * (float)TT);
        out[(size_t)TT * HH + 0] = aux;
        out[(size_t)TT * HH + 1] = g_zsum / (float)TT;
    }
}

// -------------------- launch --------------------
extern "C" void kernel_launch(void* const* d_in, const int* in_sizes, int n_in,
                              void* d_out, int out_size) {
    const float* x   = (const float*)d_in[0];
    const float* rw  = (const float*)d_in[1];
    const float* gw  = (const float*)d_in[2];
    const float* uw  = (const float*)d_in[3];
    const float* dw  = (const float*)d_in[4];
    const float* sgw = (const float*)d_in[5];
    const float* suw = (const float*)d_in[6];
    const float* sdw = (const float*)d_in[7];
    float* out = (float*)d_out;

    k_init<<<1, 32>>>();
    k_router<<<TT / 4, 128>>>(x, rw, out);
    // GEMM1: z in [0,8): routed experts; z==8: shared expert
    k_gemm1_tc<<<dim3(II / 64, TT / 128, EE + 1), 256>>>(x, gw, uw, sgw, suw);
    // shared down-proj writes out (initializes routed region)...
    k_gemm2_tc<<<dim3(HH / 128, TT / 128, 1), 256>>>(dw, sdw, out, 1);
    // ...then routed experts atomically accumulate on top
    k_gemm2_tc<<<dim3(HH / 128, TT / 128, EE), 256>>>(dw, sdw, out, 0);
    k_final<<<1, 32>>>(out);
}